// round 13
// baseline (speedup 1.0000x reference)
#include <cuda_runtime.h>
#include <float.h>
#include <math.h>

// Problem constants
#define E    256
#define C    128
#define HW   3136          // 56*56
#define HW4  784           // float4s per channel
#define NC   200
#define NP   512
#define NL   64
#define LL   8
#define ED   256           // EDGE_DIM = 2C
#define LIN  258           // LOOP_IN
#define FEAT 64
#define ZW   192           // 64 outputs * 3 taps
#define ZPAD 196           // padded row stride
#define POOLB 1024         // single-wave pool grid; 8 warps/block, 4 ch/warp

// Output layout (flattened concat of reference return tuple)
#define OFF_OUT 0
#define OFF_EC  (E*C)            // 32768
#define OFF_LC  (OFF_EC + E)     // 33024
#define OFF_LE  (OFF_LC + NL)    // 33088

// Device scratch (no allocation allowed)
__device__ float g_edge_x[E*ED];
__device__ float g_z[NC*ZW];         // per-corner conv0 partials z[c][o*3+k]
__device__ float g_h2[NL*64*LL];     // conv1 output
__device__ float g_loop_feat[NL*FEAT];
__device__ float g_Wt[LIN*ZW];       // transposed conv0 weights Wt[i][o*3+k]
__device__ unsigned g_cnt;           // conv2 last-block counter (self-resetting)

// ---------------------------------------------------------------------------
// Kernel 1 (fused): blocks [0, POOLB) = persistent warp pool, 4 channels per
// warp with 4 independent accumulators (411 MB HBM read at max MLP, single
// wave); blocks [POOLB, POOLB+NL) = loop-edge incidence; rest = conv0 weight
// transpose. Small blocks ride free under the DRAM-bound pool.
// ---------------------------------------------------------------------------
__global__ void k_pool_prep(const float* __restrict__ img,
                            const float* __restrict__ coord,
                            const int* __restrict__ loops,
                            const int* __restrict__ edge_corner,
                            const float* __restrict__ Wc0,
                            float* __restrict__ out) {
    int t = threadIdx.x;
    if (blockIdx.x < POOLB) {
        int wid = t >> 5, lane = t & 31;
        int w = blockIdx.x * 8 + wid;          // warp id: owns channels 4w..4w+3
        const float4* b0 = (const float4*)img + (size_t)w * 4 * HW4;
        const float4* b1 = b0 + HW4;
        const float4* b2 = b1 + HW4;
        const float4* b3 = b2 + HW4;
        float m0 = -FLT_MAX, m1 = -FLT_MAX, m2 = -FLT_MAX, m3 = -FLT_MAX;
        int i = lane;
        #pragma unroll 4
        for (; i < 768; i += 32) {
            float4 v0 = b0[i], v1 = b1[i], v2 = b2[i], v3 = b3[i];
            m0 = fmaxf(m0, fmaxf(fmaxf(v0.x, v0.y), fmaxf(v0.z, v0.w)));
            m1 = fmaxf(m1, fmaxf(fmaxf(v1.x, v1.y), fmaxf(v1.z, v1.w)));
            m2 = fmaxf(m2, fmaxf(fmaxf(v2.x, v2.y), fmaxf(v2.z, v2.w)));
            m3 = fmaxf(m3, fmaxf(fmaxf(v3.x, v3.y), fmaxf(v3.z, v3.w)));
        }
        if (i < HW4) {                         // tail: 16 lanes
            float4 v0 = b0[i], v1 = b1[i], v2 = b2[i], v3 = b3[i];
            m0 = fmaxf(m0, fmaxf(fmaxf(v0.x, v0.y), fmaxf(v0.z, v0.w)));
            m1 = fmaxf(m1, fmaxf(fmaxf(v1.x, v1.y), fmaxf(v1.z, v1.w)));
            m2 = fmaxf(m2, fmaxf(fmaxf(v2.x, v2.y), fmaxf(v2.z, v2.w)));
            m3 = fmaxf(m3, fmaxf(fmaxf(v3.x, v3.y), fmaxf(v3.z, v3.w)));
        }
        #pragma unroll
        for (int off = 16; off > 0; off >>= 1) {
            m0 = fmaxf(m0, __shfl_xor_sync(0xFFFFFFFFu, m0, off));
            m1 = fmaxf(m1, __shfl_xor_sync(0xFFFFFFFFu, m1, off));
            m2 = fmaxf(m2, __shfl_xor_sync(0xFFFFFFFFu, m2, off));
            m3 = fmaxf(m3, __shfl_xor_sync(0xFFFFFFFFu, m3, off));
        }
        if (lane < 4) {
            int ec = w * 4 + lane;
            float m = (lane == 0) ? m0 : (lane == 1) ? m1 : (lane == 2) ? m2 : m3;
            int e = ec >> 7, c = ec & 127;
            g_edge_x[e * ED + c]     = m;
            g_edge_x[e * ED + C + c] = coord[ec];
        }
    } else if (blockIdx.x < POOLB + NL) {
        int l = blockIdx.x - POOLB, e = t;     // 256 threads = edges
        __shared__ int ci[LL];
        if (e < LL) ci[e] = loops[l * LL + e];
        __syncthreads();
        int a = edge_corner[2 * e], b = edge_corner[2 * e + 1];
        float r = 0.f;
        #pragma unroll
        for (int j = 0; j < LL; j++) {
            int cj = ci[j];
            int cp = ci[(j + LL - 1) & 7];
            int cn = ci[(j + 1) & 7];
            if (cj == a && (cp == b || cn == b)) r = 1.f;
        }
        out[OFF_LE + l * E + e] = r;
    } else {
        int base = (blockIdx.x - POOLB - NL) * 512;
        #pragma unroll
        for (int k = 0; k < 2; k++) {
            int d = base + t + k * 256;
            if (d < LIN * ZW) {
                int i = d / ZW, ok = d - i * ZW;
                int o = ok / 3, kk = ok - o * 3;
                g_Wt[d] = Wc0[(o * LIN + i) * 3 + kk];
            }
        }
    }
}

// ---------------------------------------------------------------------------
// Kernel 2 (fused): blocks [0,E) = edge-conf MLP;
// blocks [E, E+NC) = corner scatter-mean + per-corner conv0 GEMM row.
// ---------------------------------------------------------------------------
__global__ void k_edge_corner(const float* __restrict__ W1, const float* __restrict__ b1,
                              const float* __restrict__ W2, const float* __restrict__ b2,
                              const int* __restrict__ pairs,
                              const float* __restrict__ corners,
                              float* __restrict__ out) {
    int t = threadIdx.x;
    if (blockIdx.x < E) {
        int e = blockIdx.x;
        __shared__ float sx[ED];
        __shared__ float sr[64];
        for (int i = t; i < ED; i += 256) sx[i] = g_edge_x[e * ED + i];
        __syncthreads();
        int ks = t & 3, o = t >> 2;
        float acc = 0.f;
        #pragma unroll 16
        for (int i = ks; i < ED; i += 4) acc += sx[i] * W1[o * ED + i];
        acc += __shfl_down_sync(0xFFFFFFFFu, acc, 1);
        acc += __shfl_down_sync(0xFFFFFFFFu, acc, 2);
        if (ks == 0) sr[o] = fmaxf(acc + b1[o], 0.f) * W2[o];
        __syncthreads();
        if (t < 32) {
            float v = sr[t] + sr[t + 32];
            #pragma unroll
            for (int off = 16; off > 0; off >>= 1)
                v += __shfl_xor_sync(0xFFFFFFFFu, v, off);
            if (t == 0) out[OFF_EC + e] = 1.f / (1.f + expf(-(v + b2[0])));
        }
    } else {
        int c = blockIdx.x - E;
        __shared__ unsigned mask[NP / 32];
        __shared__ int sedge[NP];
        __shared__ float sfeat[LIN];
        if (t < NP / 32) mask[t] = 0u;
        __syncthreads();
        #pragma unroll
        for (int k = 0; k < 2; k++) {
            int p = t + k * 256;
            int2 pr = ((const int2*)pairs)[p];
            sedge[p] = pr.y;
            if (pr.x == c) atomicOr(&mask[p >> 5], 1u << (p & 31));
        }
        __syncthreads();
        float sum = 0.f, cnt = 0.f;
        #pragma unroll
        for (int w = 0; w < NP / 32; w++) {
            unsigned m = mask[w];
            while (m) {
                int b = __ffs(m) - 1;
                m &= m - 1;
                sum += g_edge_x[sedge[w * 32 + b] * ED + t];
                cnt += 1.f;
            }
        }
        sfeat[t] = sum / fmaxf(cnt, 1.f);
        if (t < 2) sfeat[ED + t] = corners[c * 2 + t];
        __syncthreads();
        if (t < ZW) {
            float a0 = 0.f, a1 = 0.f, a2 = 0.f, a3 = 0.f;
            int i = 0;
            #pragma unroll 2
            for (; i + 3 < LIN; i += 4) {
                a0 += sfeat[i]     * g_Wt[(i    ) * ZW + t];
                a1 += sfeat[i + 1] * g_Wt[(i + 1) * ZW + t];
                a2 += sfeat[i + 2] * g_Wt[(i + 2) * ZW + t];
                a3 += sfeat[i + 3] * g_Wt[(i + 3) * ZW + t];
            }
            for (; i < LIN; i++) a0 += sfeat[i] * g_Wt[i * ZW + t];
            g_z[c * ZW + t] = (a0 + a1) + (a2 + a3);
        }
    }
}

// ---------------------------------------------------------------------------
// Kernel 3: conv0 assembly + conv1 (wide). grid = (4, NL), 512 threads =
// (ks:4, j:8, o_local:16). 16 iters/thread + shfl reduce.
// ---------------------------------------------------------------------------
__global__ void k_conv1(const int* __restrict__ loops,
                        const float* __restrict__ bc0,
                        const float* __restrict__ Wc1, const float* __restrict__ bc1) {
    int l = blockIdx.y, bo = blockIdx.x, t = threadIdx.x;
    __shared__ int   ci[LL];
    __shared__ float zz[LL * ZPAD];
    __shared__ float hA[64 * LL];
    if (t < LL) ci[t] = loops[l * LL + t];
    __syncthreads();
    for (int idx = t; idx < LL * ZW; idx += 512) {
        int jj = idx / ZW, ok = idx - jj * ZW;
        zz[jj * ZPAD + ok] = g_z[ci[jj] * ZW + ok];
    }
    __syncthreads();
    {   // conv0 assembly
        int o = t >> 3, j = t & 7;
        int jm = j - 1; if (jm < 0) jm = 1;
        int jp = j + 1; if (jp > 7) jp = 6;
        float a = bc0[o] + zz[jm * ZPAD + o * 3]
                         + zz[j  * ZPAD + o * 3 + 1]
                         + zz[jp * ZPAD + o * 3 + 2];
        hA[o * LL + j] = fmaxf(a, 0.f);
    }
    __syncthreads();

    int ks = t & 3, j = (t >> 2) & 7, ol = t >> 5;
    int o = bo * 16 + ol;
    int jm = j - 1; if (jm < 0) jm = 1;
    int jp = j + 1; if (jp > 7) jp = 6;
    float acc = 0.f;
    #pragma unroll
    for (int i = ks; i < 64; i += 4) {
        const float* w = Wc1 + (o * 64 + i) * 3;
        acc += w[0] * hA[i * 8 + jm] + w[1] * hA[i * 8 + j] + w[2] * hA[i * 8 + jp];
    }
    acc += __shfl_down_sync(0xFFFFFFFFu, acc, 1);
    acc += __shfl_down_sync(0xFFFFFFFFu, acc, 2);
    if (ks == 0)
        g_h2[(l * 64 + o) * LL + j] = fmaxf(acc + bc1[o], 0.f);
}

// ---------------------------------------------------------------------------
// Kernel 4: conv2 (wide) with fused max-over-L; last finishing block also
// runs the loop-conf MLP for all 64 loops (saves one launch).
// grid = (4, NL), 512 threads = (ks:4, j:8, o_local:16).
// ---------------------------------------------------------------------------
__global__ void k_conv2(const float* __restrict__ Wc2, const float* __restrict__ bc2,
                        const float* __restrict__ Wl1, const float* __restrict__ bl1,
                        const float* __restrict__ Wl2, const float* __restrict__ bl2,
                        float* __restrict__ out) {
    int l = blockIdx.y, bo = blockIdx.x, t = threadIdx.x;
    __shared__ float hB[64 * LL];
    hB[t] = g_h2[l * 512 + t];
    __syncthreads();

    int ks = t & 3, j = (t >> 2) & 7, ol = t >> 5;
    int o = bo * 16 + ol;
    int jm = j - 1; if (jm < 0) jm = 1;
    int jp = j + 1; if (jp > 7) jp = 6;
    float acc = 0.f;
    #pragma unroll
    for (int i = ks; i < 64; i += 4) {
        const float* w = Wc2 + (o * 64 + i) * 3;
        acc += w[0] * hB[i * 8 + jm] + w[1] * hB[i * 8 + j] + w[2] * hB[i * 8 + jp];
    }
    acc += __shfl_down_sync(0xFFFFFFFFu, acc, 1);
    acc += __shfl_down_sync(0xFFFFFFFFu, acc, 2);
    float v = (ks == 0) ? fmaxf(acc + bc2[o], 0.f) : -FLT_MAX;
    v = fmaxf(v, __shfl_xor_sync(0xFFFFFFFFu, v, 4));
    v = fmaxf(v, __shfl_xor_sync(0xFFFFFFFFu, v, 8));
    v = fmaxf(v, __shfl_xor_sync(0xFFFFFFFFu, v, 16));
    if ((t & 31) == 0) g_loop_feat[l * FEAT + o] = v;

    // ---- last-block loop-conf MLP ----
    __threadfence();
    __syncthreads();
    __shared__ bool last;
    if (t == 0) {
        unsigned prev = atomicAdd(&g_cnt, 1u);
        last = (prev == 4u * NL - 1u);
        if (last) atomicExch(&g_cnt, 0u);      // self-reset for graph replay
    }
    __syncthreads();
    if (last) {
        __threadfence();                       // acquire all g_loop_feat writes
        int wid = t >> 5, lane = t & 31;       // 16 warps, 4 loops each
        for (int ll = wid; ll < NL; ll += 16) {
            float f0 = g_loop_feat[ll * FEAT + lane];
            float f1 = g_loop_feat[ll * FEAT + 32 + lane];
            float a = bl1[lane];
            #pragma unroll
            for (int i = 0; i < 32; i++) {
                a += __shfl_sync(0xFFFFFFFFu, f0, i) * Wl1[lane * 64 + i];
                a += __shfl_sync(0xFFFFFFFFu, f1, i) * Wl1[lane * 64 + 32 + i];
            }
            float s = fmaxf(a, 0.f) * Wl2[lane];
            #pragma unroll
            for (int off = 16; off > 0; off >>= 1)
                s += __shfl_xor_sync(0xFFFFFFFFu, s, off);
            if (lane == 0) out[OFF_LC + ll] = 1.f / (1.f + expf(-(s + bl2[0])));
        }
    }
}

// ---------------------------------------------------------------------------
// Kernel 5: confidence-weighted loop-feature average per edge + final 1x1 conv
// ---------------------------------------------------------------------------
__global__ void k_final(const float* __restrict__ coord,
                        const float* __restrict__ Wagg,
                        float* __restrict__ out) {
    int e = blockIdx.x, t = threadIdx.x;       // 128 threads
    __shared__ float cat[C + FEAT];
    __shared__ float lconf[NL];
    if (t < NL) lconf[t] = out[OFF_LC + t];
    if (t < C)  cat[t]   = coord[e * C + t];
    __syncthreads();
    if (t < FEAT) {
        float num = 0.f, den = 0.f;
        #pragma unroll 8
        for (int l = 0; l < NL; l++) {
            float w = lconf[l] * out[OFF_LE + l * E + e];
            num += w * g_loop_feat[l * FEAT + t];
            den += w;
        }
        cat[C + t] = num / fmaxf(den, 1e-4f);
    }
    __syncthreads();
    float acc = 0.f;
    const float* w = Wagg + t * (C + FEAT);
    #pragma unroll 8
    for (int i = 0; i < C + FEAT; i++) acc += cat[i] * w[i];
    out[e * C + t] = fmaxf(acc, 0.f);
}

// ---------------------------------------------------------------------------
extern "C" void kernel_launch(void* const* d_in, const int* in_sizes, int n_in,
                              void* d_out, int out_size) {
    const float* image_x = (const float*)d_in[0];
    const float* coord_x = (const float*)d_in[1];
    const float* corners = (const float*)d_in[2];
    const int*   pairs   = (const int*)  d_in[3];
    const int*   e_crn   = (const int*)  d_in[4];
    const int*   loops   = (const int*)  d_in[5];
    const float* W_ep1 = (const float*)d_in[6];
    const float* b_ep1 = (const float*)d_in[7];
    const float* W_ep2 = (const float*)d_in[8];
    const float* b_ep2 = (const float*)d_in[9];
    const float* Wc0 = (const float*)d_in[10];
    const float* bc0 = (const float*)d_in[11];
    const float* Wc1 = (const float*)d_in[12];
    const float* bc1 = (const float*)d_in[13];
    const float* Wc2 = (const float*)d_in[14];
    const float* bc2 = (const float*)d_in[15];
    const float* Wl1 = (const float*)d_in[16];
    const float* bl1 = (const float*)d_in[17];
    const float* Wl2 = (const float*)d_in[18];
    const float* bl2 = (const float*)d_in[19];
    const float* Wagg = (const float*)d_in[20];
    float* out = (float*)d_out;

    k_pool_prep  <<<POOLB + NL + 97, 256>>>(image_x, coord_x, loops, e_crn, Wc0, out);
    k_edge_corner<<<E + NC, 256>>>(W_ep1, b_ep1, W_ep2, b_ep2, pairs, corners, out);
    {
        dim3 grid(4, NL);
        k_conv1 <<<grid, 512>>>(loops, bc0, Wc1, bc1);
        k_conv2 <<<grid, 512>>>(Wc2, bc2, Wl1, bl1, Wl2, bl2, out);
    }
    k_final      <<<E, 128>>>(coord_x, Wagg, out);
}

// round 16
// speedup vs baseline: 1.2484x; 1.2484x over previous
#include <cuda_runtime.h>
#include <float.h>
#include <math.h>

// Problem constants
#define E    256
#define C    128
#define HW   3136          // 56*56
#define HW4  784           // float4s per channel
#define NC   200
#define NP   512
#define NL   64
#define LL   8
#define ED   256           // EDGE_DIM = 2C
#define LIN  258           // LOOP_IN
#define FEAT 64
#define ZW   192           // 64 outputs * 3 taps
#define ZPAD 196           // padded row stride
#define POOLB (E*C/16)     // 2048 pool blocks; 8 warps/block, 2 channels/warp

// Output layout (flattened concat of reference return tuple)
#define OFF_OUT 0
#define OFF_EC  (E*C)            // 32768
#define OFF_LC  (OFF_EC + E)     // 33024
#define OFF_LE  (OFF_LC + NL)    // 33088

// Device scratch (no allocation allowed)
__device__ float g_edge_x[E*ED];
__device__ float g_z[NC*ZW];         // per-corner conv0 partials z[c][o*3+k]
__device__ float g_h2[NL*64*LL];     // conv1 output
__device__ float g_loop_feat[NL*FEAT];
__device__ float g_Wt[LIN*ZW];       // transposed conv0 weights Wt[i][o*3+k]

// ---------------------------------------------------------------------------
// Kernel 1 (fused): blocks [0, POOLB) = warp pool, 2 channels per warp with
// 2 independent accumulators (411 MB HBM read); blocks [POOLB, POOLB+NL) =
// loop-edge incidence; rest = conv0 weight transpose.
// ---------------------------------------------------------------------------
__global__ void k_pool_prep(const float* __restrict__ img,
                            const float* __restrict__ coord,
                            const int* __restrict__ loops,
                            const int* __restrict__ edge_corner,
                            const float* __restrict__ Wc0,
                            float* __restrict__ out) {
    int t = threadIdx.x;
    if (blockIdx.x < POOLB) {
        int wid = t >> 5, lane = t & 31;
        int w = blockIdx.x * 8 + wid;          // warp owns channels 2w, 2w+1
        const float4* b0 = (const float4*)img + (size_t)w * 2 * HW4;
        const float4* b1 = b0 + HW4;
        float m0 = -FLT_MAX, m1 = -FLT_MAX;
        int i = lane;
        #pragma unroll 4
        for (; i < 768; i += 32) {
            float4 v0 = b0[i], v1 = b1[i];
            m0 = fmaxf(m0, fmaxf(fmaxf(v0.x, v0.y), fmaxf(v0.z, v0.w)));
            m1 = fmaxf(m1, fmaxf(fmaxf(v1.x, v1.y), fmaxf(v1.z, v1.w)));
        }
        if (i < HW4) {                         // tail: 16 lanes
            float4 v0 = b0[i], v1 = b1[i];
            m0 = fmaxf(m0, fmaxf(fmaxf(v0.x, v0.y), fmaxf(v0.z, v0.w)));
            m1 = fmaxf(m1, fmaxf(fmaxf(v1.x, v1.y), fmaxf(v1.z, v1.w)));
        }
        #pragma unroll
        for (int off = 16; off > 0; off >>= 1) {
            m0 = fmaxf(m0, __shfl_xor_sync(0xFFFFFFFFu, m0, off));
            m1 = fmaxf(m1, __shfl_xor_sync(0xFFFFFFFFu, m1, off));
        }
        if (lane < 2) {
            int ec = w * 2 + lane;
            float m = (lane == 0) ? m0 : m1;
            int e = ec >> 7, c = ec & 127;
            g_edge_x[e * ED + c]     = m;
            g_edge_x[e * ED + C + c] = coord[ec];
        }
    } else if (blockIdx.x < POOLB + NL) {
        int l = blockIdx.x - POOLB, e = t;     // 256 threads = edges
        __shared__ int ci[LL];
        if (e < LL) ci[e] = loops[l * LL + e];
        __syncthreads();
        int a = edge_corner[2 * e], b = edge_corner[2 * e + 1];
        float r = 0.f;
        #pragma unroll
        for (int j = 0; j < LL; j++) {
            int cj = ci[j];
            int cp = ci[(j + LL - 1) & 7];
            int cn = ci[(j + 1) & 7];
            if (cj == a && (cp == b || cn == b)) r = 1.f;
        }
        out[OFF_LE + l * E + e] = r;
    } else {
        int base = (blockIdx.x - POOLB - NL) * 512;
        #pragma unroll
        for (int k = 0; k < 2; k++) {
            int d = base + t + k * 256;
            if (d < LIN * ZW) {
                int i = d / ZW, ok = d - i * ZW;
                int o = ok / 3, kk = ok - o * 3;
                g_Wt[d] = Wc0[(o * LIN + i) * 3 + kk];
            }
        }
    }
}

// ---------------------------------------------------------------------------
// Kernel 2 (fused): blocks [0,E) = edge-conf MLP;
// blocks [E, E+NC) = corner scatter-mean + per-corner conv0 GEMM row.
// ---------------------------------------------------------------------------
__global__ void k_edge_corner(const float* __restrict__ W1, const float* __restrict__ b1,
                              const float* __restrict__ W2, const float* __restrict__ b2,
                              const int* __restrict__ pairs,
                              const float* __restrict__ corners,
                              float* __restrict__ out) {
    int t = threadIdx.x;
    if (blockIdx.x < E) {
        int e = blockIdx.x;
        __shared__ float sx[ED];
        __shared__ float sr[64];
        for (int i = t; i < ED; i += 256) sx[i] = g_edge_x[e * ED + i];
        __syncthreads();
        int ks = t & 3, o = t >> 2;
        float acc = 0.f;
        #pragma unroll 16
        for (int i = ks; i < ED; i += 4) acc += sx[i] * W1[o * ED + i];
        acc += __shfl_down_sync(0xFFFFFFFFu, acc, 1);
        acc += __shfl_down_sync(0xFFFFFFFFu, acc, 2);
        if (ks == 0) sr[o] = fmaxf(acc + b1[o], 0.f) * W2[o];
        __syncthreads();
        if (t < 32) {
            float v = sr[t] + sr[t + 32];
            #pragma unroll
            for (int off = 16; off > 0; off >>= 1)
                v += __shfl_xor_sync(0xFFFFFFFFu, v, off);
            if (t == 0) out[OFF_EC + e] = 1.f / (1.f + expf(-(v + b2[0])));
        }
    } else {
        int c = blockIdx.x - E;
        __shared__ unsigned mask[NP / 32];
        __shared__ int sedge[NP];
        __shared__ float sfeat[LIN];
        if (t < NP / 32) mask[t] = 0u;
        __syncthreads();
        #pragma unroll
        for (int k = 0; k < 2; k++) {
            int p = t + k * 256;
            int2 pr = ((const int2*)pairs)[p];
            sedge[p] = pr.y;
            if (pr.x == c) atomicOr(&mask[p >> 5], 1u << (p & 31));
        }
        __syncthreads();
        float sum = 0.f, cnt = 0.f;
        #pragma unroll
        for (int w = 0; w < NP / 32; w++) {
            unsigned m = mask[w];
            while (m) {
                int b = __ffs(m) - 1;
                m &= m - 1;
                sum += g_edge_x[sedge[w * 32 + b] * ED + t];
                cnt += 1.f;
            }
        }
        sfeat[t] = sum / fmaxf(cnt, 1.f);
        if (t < 2) sfeat[ED + t] = corners[c * 2 + t];
        __syncthreads();
        if (t < ZW) {
            float a0 = 0.f, a1 = 0.f, a2 = 0.f, a3 = 0.f;
            int i = 0;
            #pragma unroll 2
            for (; i + 3 < LIN; i += 4) {
                a0 += sfeat[i]     * g_Wt[(i    ) * ZW + t];
                a1 += sfeat[i + 1] * g_Wt[(i + 1) * ZW + t];
                a2 += sfeat[i + 2] * g_Wt[(i + 2) * ZW + t];
                a3 += sfeat[i + 3] * g_Wt[(i + 3) * ZW + t];
            }
            for (; i < LIN; i++) a0 += sfeat[i] * g_Wt[i * ZW + t];
            g_z[c * ZW + t] = (a0 + a1) + (a2 + a3);
        }
    }
}

// ---------------------------------------------------------------------------
// Kernel 3: conv0 assembly + conv1 (wide). grid = (4, NL), 512 threads =
// (ks:4, j:8, o_local:16). 16 iters/thread + shfl reduce.
// ---------------------------------------------------------------------------
__global__ void k_conv1(const int* __restrict__ loops,
                        const float* __restrict__ bc0,
                        const float* __restrict__ Wc1, const float* __restrict__ bc1) {
    int l = blockIdx.y, bo = blockIdx.x, t = threadIdx.x;
    __shared__ int   ci[LL];
    __shared__ float zz[LL * ZPAD];
    __shared__ float hA[64 * LL];
    if (t < LL) ci[t] = loops[l * LL + t];
    __syncthreads();
    for (int idx = t; idx < LL * ZW; idx += 512) {
        int jj = idx / ZW, ok = idx - jj * ZW;
        zz[jj * ZPAD + ok] = g_z[ci[jj] * ZW + ok];
    }
    __syncthreads();
    {   // conv0 assembly
        int o = t >> 3, j = t & 7;
        int jm = j - 1; if (jm < 0) jm = 1;
        int jp = j + 1; if (jp > 7) jp = 6;
        float a = bc0[o] + zz[jm * ZPAD + o * 3]
                         + zz[j  * ZPAD + o * 3 + 1]
                         + zz[jp * ZPAD + o * 3 + 2];
        hA[o * LL + j] = fmaxf(a, 0.f);
    }
    __syncthreads();

    int ks = t & 3, j = (t >> 2) & 7, ol = t >> 5;
    int o = bo * 16 + ol;
    int jm = j - 1; if (jm < 0) jm = 1;
    int jp = j + 1; if (jp > 7) jp = 6;
    float acc = 0.f;
    #pragma unroll
    for (int i = ks; i < 64; i += 4) {
        const float* w = Wc1 + (o * 64 + i) * 3;
        acc += w[0] * hA[i * 8 + jm] + w[1] * hA[i * 8 + j] + w[2] * hA[i * 8 + jp];
    }
    acc += __shfl_down_sync(0xFFFFFFFFu, acc, 1);
    acc += __shfl_down_sync(0xFFFFFFFFu, acc, 2);
    if (ks == 0)
        g_h2[(l * 64 + o) * LL + j] = fmaxf(acc + bc1[o], 0.f);
}

// ---------------------------------------------------------------------------
// Kernel 4: conv2 (wide) with max-over-L fused via warp shuffles.
// grid = (4, NL), 512 threads = (ks:4, j:8, o_local:16).
// ---------------------------------------------------------------------------
__global__ void k_conv2(const float* __restrict__ Wc2, const float* __restrict__ bc2) {
    int l = blockIdx.y, bo = blockIdx.x, t = threadIdx.x;
    __shared__ float hB[64 * LL];
    hB[t] = g_h2[l * 512 + t];
    __syncthreads();

    int ks = t & 3, j = (t >> 2) & 7, ol = t >> 5;
    int o = bo * 16 + ol;
    int jm = j - 1; if (jm < 0) jm = 1;
    int jp = j + 1; if (jp > 7) jp = 6;
    float acc = 0.f;
    #pragma unroll
    for (int i = ks; i < 64; i += 4) {
        const float* w = Wc2 + (o * 64 + i) * 3;
        acc += w[0] * hB[i * 8 + jm] + w[1] * hB[i * 8 + j] + w[2] * hB[i * 8 + jp];
    }
    acc += __shfl_down_sync(0xFFFFFFFFu, acc, 1);
    acc += __shfl_down_sync(0xFFFFFFFFu, acc, 2);
    float v = (ks == 0) ? fmaxf(acc + bc2[o], 0.f) : -FLT_MAX;
    v = fmaxf(v, __shfl_xor_sync(0xFFFFFFFFu, v, 4));
    v = fmaxf(v, __shfl_xor_sync(0xFFFFFFFFu, v, 8));
    v = fmaxf(v, __shfl_xor_sync(0xFFFFFFFFu, v, 16));
    if ((t & 31) == 0) g_loop_feat[l * FEAT + o] = v;
}

// ---------------------------------------------------------------------------
// Kernel 5: loop-conf MLP (tiny). grid = NL, 32 threads, register-resident.
// ---------------------------------------------------------------------------
__global__ void k_loopmlp(const float* __restrict__ Wl1, const float* __restrict__ bl1,
                          const float* __restrict__ Wl2, const float* __restrict__ bl2,
                          float* __restrict__ out) {
    int l = blockIdx.x, t = threadIdx.x;       // 32 threads
    float f0 = g_loop_feat[l * FEAT + t];
    float f1 = g_loop_feat[l * FEAT + 32 + t];
    float a = bl1[t];
    #pragma unroll
    for (int i = 0; i < 32; i++) {
        a += __shfl_sync(0xFFFFFFFFu, f0, i) * Wl1[t * 64 + i];
        a += __shfl_sync(0xFFFFFFFFu, f1, i) * Wl1[t * 64 + 32 + i];
    }
    float v = fmaxf(a, 0.f) * Wl2[t];
    #pragma unroll
    for (int off = 16; off > 0; off >>= 1)
        v += __shfl_xor_sync(0xFFFFFFFFu, v, off);
    if (t == 0) out[OFF_LC + l] = 1.f / (1.f + expf(-(v + bl2[0])));
}

// ---------------------------------------------------------------------------
// Kernel 6: confidence-weighted loop-feature average per edge + final 1x1 conv
// ---------------------------------------------------------------------------
__global__ void k_final(const float* __restrict__ coord,
                        const float* __restrict__ Wagg,
                        float* __restrict__ out) {
    int e = blockIdx.x, t = threadIdx.x;       // 128 threads
    __shared__ float cat[C + FEAT];
    __shared__ float lconf[NL];
    if (t < NL) lconf[t] = out[OFF_LC + t];
    if (t < C)  cat[t]   = coord[e * C + t];
    __syncthreads();
    if (t < FEAT) {
        float num = 0.f, den = 0.f;
        #pragma unroll 8
        for (int l = 0; l < NL; l++) {
            float w = lconf[l] * out[OFF_LE + l * E + e];
            num += w * g_loop_feat[l * FEAT + t];
            den += w;
        }
        cat[C + t] = num / fmaxf(den, 1e-4f);
    }
    __syncthreads();
    float acc = 0.f;
    const float* w = Wagg + t * (C + FEAT);
    #pragma unroll 8
    for (int i = 0; i < C + FEAT; i++) acc += cat[i] * w[i];
    out[e * C + t] = fmaxf(acc, 0.f);
}

// ---------------------------------------------------------------------------
extern "C" void kernel_launch(void* const* d_in, const int* in_sizes, int n_in,
                              void* d_out, int out_size) {
    const float* image_x = (const float*)d_in[0];
    const float* coord_x = (const float*)d_in[1];
    const float* corners = (const float*)d_in[2];
    const int*   pairs   = (const int*)  d_in[3];
    const int*   e_crn   = (const int*)  d_in[4];
    const int*   loops   = (const int*)  d_in[5];
    const float* W_ep1 = (const float*)d_in[6];
    const float* b_ep1 = (const float*)d_in[7];
    const float* W_ep2 = (const float*)d_in[8];
    const float* b_ep2 = (const float*)d_in[9];
    const float* Wc0 = (const float*)d_in[10];
    const float* bc0 = (const float*)d_in[11];
    const float* Wc1 = (const float*)d_in[12];
    const float* bc1 = (const float*)d_in[13];
    const float* Wc2 = (const float*)d_in[14];
    const float* bc2 = (const float*)d_in[15];
    const float* Wl1 = (const float*)d_in[16];
    const float* bl1 = (const float*)d_in[17];
    const float* Wl2 = (const float*)d_in[18];
    const float* bl2 = (const float*)d_in[19];
    const float* Wagg = (const float*)d_in[20];
    float* out = (float*)d_out;

    k_pool_prep  <<<POOLB + NL + 97, 256>>>(image_x, coord_x, loops, e_crn, Wc0, out);
    k_edge_corner<<<E + NC, 256>>>(W_ep1, b_ep1, W_ep2, b_ep2, pairs, corners, out);
    {
        dim3 grid(4, NL);
        k_conv1 <<<grid, 512>>>(loops, bc0, Wc1, bc1);
        k_conv2 <<<grid, 512>>>(Wc2, bc2);
    }
    k_loopmlp    <<<NL, 32>>>(Wl1, bl1, Wl2, bl2, out);
    k_final      <<<E, 128>>>(coord_x, Wagg, out);
}

// round 17
// speedup vs baseline: 1.6690x; 1.3369x over previous
#include <cuda_runtime.h>
#include <float.h>
#include <math.h>

// Problem constants
#define E    256
#define C    128
#define HW   3136          // 56*56
#define HW4  784           // float4s per channel
#define NC   200
#define NP   512
#define NL   64
#define LL   8
#define ED   256           // EDGE_DIM = 2C
#define LIN  258           // LOOP_IN
#define FEAT 64
#define ZW   192           // 64 outputs * 3 taps
#define ZPAD 196           // padded row stride
#define POOLB (E*C/8)      // 4096 pool blocks; 8 warps/block, 1 channel/warp

// Output layout (flattened concat of reference return tuple)
#define OFF_OUT 0
#define OFF_EC  (E*C)            // 32768
#define OFF_LC  (OFF_EC + E)     // 33024
#define OFF_LE  (OFF_LC + NL)    // 33088

// Device scratch (no allocation allowed)
__device__ float g_edge_x[E*ED];
__device__ float g_z[NC*ZW];         // per-corner conv0 partials z[c][o*3+k]
__device__ float g_h2[NL*64*LL];     // conv1 output
__device__ float g_loop_feat[NL*FEAT];
__device__ float g_Wt[LIN*ZW];       // transposed conv0 weights Wt[i][o*3+k]

// ---------------------------------------------------------------------------
// Kernel 1 (fused): blocks [0, POOLB) = warp-per-channel max pool (411 MB HBM
// read; evict-first streaming loads since data is read exactly once); blocks
// [POOLB, POOLB+NL) = loop-edge incidence; rest = conv0 weight transpose.
// ---------------------------------------------------------------------------
__global__ void k_pool_prep(const float* __restrict__ img,
                            const float* __restrict__ coord,
                            const int* __restrict__ loops,
                            const int* __restrict__ edge_corner,
                            const float* __restrict__ Wc0,
                            float* __restrict__ out) {
    int t = threadIdx.x;
    if (blockIdx.x < POOLB) {
        int wid = t >> 5, lane = t & 31;
        int ec = blockIdx.x * 8 + wid;         // e*C + c, one channel per warp
        const float4* p = (const float4*)img + (size_t)ec * HW4;
        float m = -FLT_MAX;
        int i = lane;
        #pragma unroll 6
        for (; i < 768; i += 32) {
            float4 v = __ldcs(p + i);          // streaming: read-once data
            m = fmaxf(m, fmaxf(fmaxf(v.x, v.y), fmaxf(v.z, v.w)));
        }
        if (i < HW4) {                         // tail (784-768 -> 16 lanes)
            float4 v = __ldcs(p + i);
            m = fmaxf(m, fmaxf(fmaxf(v.x, v.y), fmaxf(v.z, v.w)));
        }
        #pragma unroll
        for (int off = 16; off > 0; off >>= 1)
            m = fmaxf(m, __shfl_xor_sync(0xFFFFFFFFu, m, off));
        if (lane == 0) {
            int e = ec >> 7, c = ec & 127;
            g_edge_x[e * ED + c]     = m;
            g_edge_x[e * ED + C + c] = coord[ec];
        }
    } else if (blockIdx.x < POOLB + NL) {
        int l = blockIdx.x - POOLB, e = t;     // 256 threads = edges
        __shared__ int ci[LL];
        if (e < LL) ci[e] = loops[l * LL + e];
        __syncthreads();
        int a = edge_corner[2 * e], b = edge_corner[2 * e + 1];
        float r = 0.f;
        #pragma unroll
        for (int j = 0; j < LL; j++) {
            int cj = ci[j];
            int cp = ci[(j + LL - 1) & 7];
            int cn = ci[(j + 1) & 7];
            if (cj == a && (cp == b || cn == b)) r = 1.f;
        }
        out[OFF_LE + l * E + e] = r;
    } else {
        int base = (blockIdx.x - POOLB - NL) * 512;
        #pragma unroll
        for (int k = 0; k < 2; k++) {
            int d = base + t + k * 256;
            if (d < LIN * ZW) {
                int i = d / ZW, ok = d - i * ZW;
                int o = ok / 3, kk = ok - o * 3;
                g_Wt[d] = Wc0[(o * LIN + i) * 3 + kk];
            }
        }
    }
}

// ---------------------------------------------------------------------------
// Kernel 2 (fused): blocks [0,E) = edge-conf MLP;
// blocks [E, E+NC) = corner scatter-mean + per-corner conv0 GEMM row.
// ---------------------------------------------------------------------------
__global__ void k_edge_corner(const float* __restrict__ W1, const float* __restrict__ b1,
                              const float* __restrict__ W2, const float* __restrict__ b2,
                              const int* __restrict__ pairs,
                              const float* __restrict__ corners,
                              float* __restrict__ out) {
    int t = threadIdx.x;
    if (blockIdx.x < E) {
        int e = blockIdx.x;
        __shared__ float sx[ED];
        __shared__ float sr[64];
        for (int i = t; i < ED; i += 256) sx[i] = g_edge_x[e * ED + i];
        __syncthreads();
        int ks = t & 3, o = t >> 2;
        float acc = 0.f;
        #pragma unroll 16
        for (int i = ks; i < ED; i += 4) acc += sx[i] * W1[o * ED + i];
        acc += __shfl_down_sync(0xFFFFFFFFu, acc, 1);
        acc += __shfl_down_sync(0xFFFFFFFFu, acc, 2);
        if (ks == 0) sr[o] = fmaxf(acc + b1[o], 0.f) * W2[o];
        __syncthreads();
        if (t < 32) {
            float v = sr[t] + sr[t + 32];
            #pragma unroll
            for (int off = 16; off > 0; off >>= 1)
                v += __shfl_xor_sync(0xFFFFFFFFu, v, off);
            if (t == 0) out[OFF_EC + e] = 1.f / (1.f + expf(-(v + b2[0])));
        }
    } else {
        int c = blockIdx.x - E;
        __shared__ unsigned mask[NP / 32];
        __shared__ int sedge[NP];
        __shared__ float sfeat[LIN];
        if (t < NP / 32) mask[t] = 0u;
        __syncthreads();
        #pragma unroll
        for (int k = 0; k < 2; k++) {
            int p = t + k * 256;
            int2 pr = ((const int2*)pairs)[p];
            sedge[p] = pr.y;
            if (pr.x == c) atomicOr(&mask[p >> 5], 1u << (p & 31));
        }
        __syncthreads();
        float sum = 0.f, cnt = 0.f;
        #pragma unroll
        for (int w = 0; w < NP / 32; w++) {
            unsigned m = mask[w];
            while (m) {
                int b = __ffs(m) - 1;
                m &= m - 1;
                sum += g_edge_x[sedge[w * 32 + b] * ED + t];
                cnt += 1.f;
            }
        }
        sfeat[t] = sum / fmaxf(cnt, 1.f);
        if (t < 2) sfeat[ED + t] = corners[c * 2 + t];
        __syncthreads();
        if (t < ZW) {
            float a0 = 0.f, a1 = 0.f, a2 = 0.f, a3 = 0.f;
            int i = 0;
            #pragma unroll 2
            for (; i + 3 < LIN; i += 4) {
                a0 += sfeat[i]     * g_Wt[(i    ) * ZW + t];
                a1 += sfeat[i + 1] * g_Wt[(i + 1) * ZW + t];
                a2 += sfeat[i + 2] * g_Wt[(i + 2) * ZW + t];
                a3 += sfeat[i + 3] * g_Wt[(i + 3) * ZW + t];
            }
            for (; i < LIN; i++) a0 += sfeat[i] * g_Wt[i * ZW + t];
            g_z[c * ZW + t] = (a0 + a1) + (a2 + a3);
        }
    }
}

// ---------------------------------------------------------------------------
// Kernel 3: conv0 assembly + conv1 (wide). grid = (4, NL), 512 threads =
// (ks:4, j:8, o_local:16). 16 iters/thread + shfl reduce.
// ---------------------------------------------------------------------------
__global__ void k_conv1(const int* __restrict__ loops,
                        const float* __restrict__ bc0,
                        const float* __restrict__ Wc1, const float* __restrict__ bc1) {
    int l = blockIdx.y, bo = blockIdx.x, t = threadIdx.x;
    __shared__ int   ci[LL];
    __shared__ float zz[LL * ZPAD];
    __shared__ float hA[64 * LL];
    if (t < LL) ci[t] = loops[l * LL + t];
    __syncthreads();
    for (int idx = t; idx < LL * ZW; idx += 512) {
        int jj = idx / ZW, ok = idx - jj * ZW;
        zz[jj * ZPAD + ok] = g_z[ci[jj] * ZW + ok];
    }
    __syncthreads();
    {   // conv0 assembly
        int o = t >> 3, j = t & 7;
        int jm = j - 1; if (jm < 0) jm = 1;
        int jp = j + 1; if (jp > 7) jp = 6;
        float a = bc0[o] + zz[jm * ZPAD + o * 3]
                         + zz[j  * ZPAD + o * 3 + 1]
                         + zz[jp * ZPAD + o * 3 + 2];
        hA[o * LL + j] = fmaxf(a, 0.f);
    }
    __syncthreads();

    int ks = t & 3, j = (t >> 2) & 7, ol = t >> 5;
    int o = bo * 16 + ol;
    int jm = j - 1; if (jm < 0) jm = 1;
    int jp = j + 1; if (jp > 7) jp = 6;
    float acc = 0.f;
    #pragma unroll
    for (int i = ks; i < 64; i += 4) {
        const float* w = Wc1 + (o * 64 + i) * 3;
        acc += w[0] * hA[i * 8 + jm] + w[1] * hA[i * 8 + j] + w[2] * hA[i * 8 + jp];
    }
    acc += __shfl_down_sync(0xFFFFFFFFu, acc, 1);
    acc += __shfl_down_sync(0xFFFFFFFFu, acc, 2);
    if (ks == 0)
        g_h2[(l * 64 + o) * LL + j] = fmaxf(acc + bc1[o], 0.f);
}

// ---------------------------------------------------------------------------
// Kernel 4: conv2 (wide) with max-over-L fused via warp shuffles.
// grid = (4, NL), 512 threads = (ks:4, j:8, o_local:16).
// ---------------------------------------------------------------------------
__global__ void k_conv2(const float* __restrict__ Wc2, const float* __restrict__ bc2) {
    int l = blockIdx.y, bo = blockIdx.x, t = threadIdx.x;
    __shared__ float hB[64 * LL];
    hB[t] = g_h2[l * 512 + t];
    __syncthreads();

    int ks = t & 3, j = (t >> 2) & 7, ol = t >> 5;
    int o = bo * 16 + ol;
    int jm = j - 1; if (jm < 0) jm = 1;
    int jp = j + 1; if (jp > 7) jp = 6;
    float acc = 0.f;
    #pragma unroll
    for (int i = ks; i < 64; i += 4) {
        const float* w = Wc2 + (o * 64 + i) * 3;
        acc += w[0] * hB[i * 8 + jm] + w[1] * hB[i * 8 + j] + w[2] * hB[i * 8 + jp];
    }
    acc += __shfl_down_sync(0xFFFFFFFFu, acc, 1);
    acc += __shfl_down_sync(0xFFFFFFFFu, acc, 2);
    float v = (ks == 0) ? fmaxf(acc + bc2[o], 0.f) : -FLT_MAX;
    v = fmaxf(v, __shfl_xor_sync(0xFFFFFFFFu, v, 4));
    v = fmaxf(v, __shfl_xor_sync(0xFFFFFFFFu, v, 8));
    v = fmaxf(v, __shfl_xor_sync(0xFFFFFFFFu, v, 16));
    if ((t & 31) == 0) g_loop_feat[l * FEAT + o] = v;
}

// ---------------------------------------------------------------------------
// Kernel 5: loop-conf MLP (tiny). grid = NL, 32 threads, register-resident.
// ---------------------------------------------------------------------------
__global__ void k_loopmlp(const float* __restrict__ Wl1, const float* __restrict__ bl1,
                          const float* __restrict__ Wl2, const float* __restrict__ bl2,
                          float* __restrict__ out) {
    int l = blockIdx.x, t = threadIdx.x;       // 32 threads
    float f0 = g_loop_feat[l * FEAT + t];
    float f1 = g_loop_feat[l * FEAT + 32 + t];
    float a = bl1[t];
    #pragma unroll
    for (int i = 0; i < 32; i++) {
        a += __shfl_sync(0xFFFFFFFFu, f0, i) * Wl1[t * 64 + i];
        a += __shfl_sync(0xFFFFFFFFu, f1, i) * Wl1[t * 64 + 32 + i];
    }
    float v = fmaxf(a, 0.f) * Wl2[t];
    #pragma unroll
    for (int off = 16; off > 0; off >>= 1)
        v += __shfl_xor_sync(0xFFFFFFFFu, v, off);
    if (t == 0) out[OFF_LC + l] = 1.f / (1.f + expf(-(v + bl2[0])));
}

// ---------------------------------------------------------------------------
// Kernel 6: confidence-weighted loop-feature average per edge + final 1x1 conv
// ---------------------------------------------------------------------------
__global__ void k_final(const float* __restrict__ coord,
                        const float* __restrict__ Wagg,
                        float* __restrict__ out) {
    int e = blockIdx.x, t = threadIdx.x;       // 128 threads
    __shared__ float cat[C + FEAT];
    __shared__ float lconf[NL];
    if (t < NL) lconf[t] = out[OFF_LC + t];
    if (t < C)  cat[t]   = coord[e * C + t];
    __syncthreads();
    if (t < FEAT) {
        float num = 0.f, den = 0.f;
        #pragma unroll 8
        for (int l = 0; l < NL; l++) {
            float w = lconf[l] * out[OFF_LE + l * E + e];
            num += w * g_loop_feat[l * FEAT + t];
            den += w;
        }
        cat[C + t] = num / fmaxf(den, 1e-4f);
    }
    __syncthreads();
    float acc = 0.f;
    const float* w = Wagg + t * (C + FEAT);
    #pragma unroll 8
    for (int i = 0; i < C + FEAT; i++) acc += cat[i] * w[i];
    out[e * C + t] = fmaxf(acc, 0.f);
}

// ---------------------------------------------------------------------------
extern "C" void kernel_launch(void* const* d_in, const int* in_sizes, int n_in,
                              void* d_out, int out_size) {
    const float* image_x = (const float*)d_in[0];
    const float* coord_x = (const float*)d_in[1];
    const float* corners = (const float*)d_in[2];
    const int*   pairs   = (const int*)  d_in[3];
    const int*   e_crn   = (const int*)  d_in[4];
    const int*   loops   = (const int*)  d_in[5];
    const float* W_ep1 = (const float*)d_in[6];
    const float* b_ep1 = (const float*)d_in[7];
    const float* W_ep2 = (const float*)d_in[8];
    const float* b_ep2 = (const float*)d_in[9];
    const float* Wc0 = (const float*)d_in[10];
    const float* bc0 = (const float*)d_in[11];
    const float* Wc1 = (const float*)d_in[12];
    const float* bc1 = (const float*)d_in[13];
    const float* Wc2 = (const float*)d_in[14];
    const float* bc2 = (const float*)d_in[15];
    const float* Wl1 = (const float*)d_in[16];
    const float* bl1 = (const float*)d_in[17];
    const float* Wl2 = (const float*)d_in[18];
    const float* bl2 = (const float*)d_in[19];
    const float* Wagg = (const float*)d_in[20];
    float* out = (float*)d_out;

    k_pool_prep  <<<POOLB + NL + 97, 256>>>(image_x, coord_x, loops, e_crn, Wc0, out);
    k_edge_corner<<<E + NC, 256>>>(W_ep1, b_ep1, W_ep2, b_ep2, pairs, corners, out);
    {
        dim3 grid(4, NL);
        k_conv1 <<<grid, 512>>>(loops, bc0, Wc1, bc1);
        k_conv2 <<<grid, 512>>>(Wc2, bc2);
    }
    k_loopmlp    <<<NL, 32>>>(Wl1, bl1, Wl2, bl2, out);
    k_final      <<<E, 128>>>(coord_x, Wagg, out);
}